// round 17
// baseline (speedup 1.0000x reference)
#include <cuda_runtime.h>
#include <cuda_fp16.h>
#include <cstdint>

// ---------------------------------------------------------------------------
// y[bi,co,ti,p] = sum_{ds,dt,ci} W[co,ci,ds,dt]*x[bi',ci,t2,p] + x
// fp16 mma.sync m16n8k16 (fp32 accum) implicit GEMM.
// R14 occupancy experiment (3rd submit; two infra failures, source verified
// three times). CTA tile 64(co) x 112(p), warp tile 16x56 (28 accums/thread),
// __launch_bounds__(256,3) -> 24 warps/SM (was 16). Proven machinery:
// BK=64 stages (two k32 sub-tiles, 64B rows, perm32 -> conflict-free LDS.128
// fragments), 3-stage cp.async, 1 sync/iter, NPAD=200 asymmetric tiles,
// cost-sorted blocks. Grid 1024.
// ---------------------------------------------------------------------------

#define CCH 1024
#define TT 4
#define HW 196
#define NPAD 200
#define SSEG 4
#define BMC 64                         // CTA M tile
#define BN 112
#define PADH 32                        // halves per sub-tile row (64B)
#define STAGES 3

#define ASUBH (BMC * PADH)             // 2048 halves per A sub-tile
#define BSUBH (BN * PADH)              // 3584 halves per B sub-tile
#define STAGE_H (2 * (ASUBH + BSUBH))  // 11264 halves per stage (BK=64)
#define STAGE_BYTES (STAGE_H * 2)      // 22528 B
#define SMEM_REQ (STAGES * STAGE_BYTES)   // 67584 B; x3 CTAs = 202752 <= 228KB

__device__ __half g_Wt[9u * CCH * CCH];      // [tap][co][perm32(ci)]
__device__ __half g_Xt[32u * NPAD * CCH];    // [z][p][perm32(ci)]

__constant__ int c_zorder[32] = {
    5, 6, 9, 10, 21, 22, 25, 26,
    4, 7, 8, 11, 20, 23, 24, 27,
    1, 2, 13, 14, 17, 18, 29, 30,
    0, 3, 12, 15, 16, 19, 28, 31
};

__device__ __forceinline__ int perm32(int ci) {
    int j = ci & 31;
    int t = (j & 7) >> 1, lo = j & 1, hi = (j >> 3) & 1, ks = j >> 4;
    return (ci & ~31) | (8 * t + 4 * ks + 2 * hi + lo);
}

// ---------------------------- helpers --------------------------------------
__device__ __forceinline__ void cp16(uint32_t dst, const void* src) {
    asm volatile("cp.async.cg.shared.global [%0], [%1], 16;" :: "r"(dst), "l"(src));
}
#define CP_COMMIT() asm volatile("cp.async.commit_group;" ::: "memory")
#define CP_WAIT1()  asm volatile("cp.async.wait_group 1;" ::: "memory")

__device__ __forceinline__ void mma_f16(float* c, uint32_t a0, uint32_t a1,
                                        uint32_t a2, uint32_t a3,
                                        uint32_t b0, uint32_t b1) {
    asm volatile(
        "mma.sync.aligned.m16n8k16.row.col.f32.f16.f16.f32 "
        "{%0,%1,%2,%3}, {%4,%5,%6,%7}, {%8,%9}, {%0,%1,%2,%3};"
        : "+f"(c[0]), "+f"(c[1]), "+f"(c[2]), "+f"(c[3])
        : "r"(a0), "r"(a1), "r"(a2), "r"(a3), "r"(b0), "r"(b1));
}

// ---------------------------- merged prep kernel ----------------------------
__global__ __launch_bounds__(256) void prep_all(const float* __restrict__ W,
                                                const float* __restrict__ x) {
    int b = blockIdx.x;
    if (b < 1024) {
        __shared__ float s[9216];
        int co = b;
        const float4* row4 = (const float4*)(W + (size_t)co * 9216);
        float4* s4 = (float4*)s;
        for (int i = threadIdx.x; i < 2304; i += 256) s4[i] = row4[i];
        __syncthreads();
        for (int tap = 0; tap < 9; tap++) {
            __half* d = g_Wt + ((size_t)tap * CCH + co) * CCH;
            for (int ci = threadIdx.x; ci < CCH; ci += 256)
                d[perm32(ci)] = __float2half(s[ci * 9 + tap]);
        }
    } else {
        __shared__ float tile[32][33];
        int bb = b - 1024;
        int pt = bb % 7;
        int cit = (bb / 7) & 31;
        int z = bb / (7 * 32);
        int p0 = pt * 32;
        int ci0 = cit * 32;
        int tx = threadIdx.x & 31, ty = threadIdx.x >> 5;   // 32 x 8
        #pragma unroll
        for (int j = 0; j < 4; j++) {
            int ci = ci0 + ty + j * 8;
            int p = p0 + tx;
            float v = 0.f;
            if (p < HW) v = x[(((size_t)((z >> 2) * CCH + ci)) * TT + (z & 3)) * HW + p];
            tile[ty + j * 8][tx] = v;
        }
        __syncthreads();
        #pragma unroll
        for (int j = 0; j < 4; j++) {
            int p = p0 + ty + j * 8;
            int ci = ci0 + tx;
            if (p < NPAD)
                g_Xt[((size_t)z * NPAD + p) * CCH + perm32(ci)] =
                    __float2half(tile[tx][ty + j * 8]);
        }
    }
}

// ---------------------------- main kernel -----------------------------------
__global__ __launch_bounds__(256, 3) void conv_mma(
    const float* __restrict__ x, float* __restrict__ out)
{
    extern __shared__ __half smem[];
    const int tid = threadIdx.x;
    const int wid = tid >> 5, lid = tid & 31;
    const int gid = lid >> 2, tig = lid & 3;
    const int warp_m = wid & 3;           // 4 warps in M: 16 rows each
    const int warp_n = wid >> 2;          // 2 warps in N: 56 cols each

    const int bidl = blockIdx.x;          // 0..1023, cost-sorted
    const int z    = c_zorder[bidl >> 5];
    const int tile = bidl & 31;
    const int ct   = tile >> 1;           // co-tile 0..15 (64 each)
    const int py   = tile & 1;            // p-tile 0..1
    const int bi = z >> 2, ti = z & 3;
    const int s_seg = bi & 3, bp = bi >> 2;
    const int co0 = ct * BMC;
    const int p0  = py * BN;

    const int ntc  = (py && warp_n) ? 4 : 7;   // 112-wide vs 88-wide tile
    const int bnr8 = (py ? 88 : 112) * 8;      // B 16B-chunks per stage

    int taps[9], zsrc[9], nv = 0;
    #pragma unroll
    for (int ds = 0; ds < 3; ds++) {
        int s2 = s_seg + ds - 1;
        if (s2 < 0 || s2 >= SSEG) continue;
        #pragma unroll
        for (int dt = 0; dt < 3; dt++) {
            int t2 = ti + dt - 1;
            if (t2 < 0 || t2 >= TT) continue;
            taps[nv] = ds * 3 + dt;
            zsrc[nv] = (bp * SSEG + s2) * TT + t2;
            nv++;
        }
    }
    const int total = nv * (CCH / 64);    // BK=64 iters

    uint32_t smem_u = (uint32_t)__cvta_generic_to_shared(smem);

    float acc[7][4];
    #pragma unroll
    for (int nt = 0; nt < 7; nt++)
        #pragma unroll
        for (int r = 0; r < 4; r++) acc[nt][r] = 0.f;

    auto load_stage = [&](int it, int st) {
        int idx = it >> 4, k0 = (it & 15) * 64;
        const __half* Wt = g_Wt + (size_t)taps[idx] * CCH * CCH + (size_t)co0 * CCH + k0;
        const __half* Xz = g_Xt + (size_t)zsrc[idx] * NPAD * CCH + (size_t)p0 * CCH + k0;
        uint32_t aB = smem_u + st * STAGE_BYTES;
        uint32_t bB = aB + 2 * (ASUBH * 2);
        // A: 512 chunks (64 rows x 8), 2 per thread
        #pragma unroll
        for (int i = 0; i < 2; i++) {
            int c = tid + i * 256;
            int row = c >> 3, cc = c & 7;
            int kb = cc >> 2, c4 = cc & 3;
            cp16(aB + kb * (ASUBH * 2) + row * 64 + c4 * 16,
                 Wt + (size_t)row * CCH + kb * 32 + c4 * 8);
        }
        // B: up to 896 chunks (112 rows x 8)
        #pragma unroll
        for (int i = 0; i < 4; i++) {
            int c = tid + i * 256;
            if (c < bnr8) {
                int row = c >> 3, cc = c & 7;
                int kb = cc >> 2, c4 = cc & 3;
                cp16(bB + kb * (BSUBH * 2) + row * 64 + c4 * 16,
                     Xz + (size_t)row * CCH + kb * 32 + c4 * 8);
            }
        }
    };

    load_stage(0, 0); CP_COMMIT();
    load_stage(1, 1); CP_COMMIT();

    const int ko = tig * 8;
    const int ar0 = (warp_m * 16 + gid) * PADH + ko;
    const int ar1 = (warp_m * 16 + gid + 8) * PADH + ko;

    int st = 0;
    for (int it = 0; it < total; it++) {
        CP_WAIT1();
        __syncthreads();           // stage (st+2)%3 now free for refill

        int nxst = st + 2; if (nxst >= STAGES) nxst -= STAGES;
        if (it + 2 < total) load_stage(it + 2, nxst);
        CP_COMMIT();

        const __half* S = smem + (size_t)st * STAGE_H;
        #pragma unroll
        for (int kb = 0; kb < 2; kb++) {
            const __half* Ak = S + kb * ASUBH;
            const __half* Bk = S + 2 * ASUBH + kb * BSUBH;

            uint4 a0 = *(const uint4*)(Ak + ar0);
            uint4 a1 = *(const uint4*)(Ak + ar1);
            uint4 bv[7];
            #pragma unroll
            for (int nt = 0; nt < 7; nt++)
                if (nt < ntc)
                    bv[nt] = *(const uint4*)(Bk + (warp_n * 56 + nt * 8 + gid) * PADH + ko);

            #pragma unroll
            for (int nt = 0; nt < 7; nt++)
                if (nt < ntc)
                    mma_f16(acc[nt], a0.x, a1.x, a0.y, a1.y, bv[nt].x, bv[nt].y);
            #pragma unroll
            for (int nt = 0; nt < 7; nt++)
                if (nt < ntc)
                    mma_f16(acc[nt], a0.z, a1.z, a0.w, a1.w, bv[nt].z, bv[nt].w);
        }
        st = st + 1; if (st >= STAGES) st = 0;
    }

    // epilogue: residual add + store
    #pragma unroll
    for (int nt = 0; nt < 7; nt++) {
        if (nt >= ntc) continue;
        int co = co0 + warp_m * 16 + gid;
        int p  = p0 + warp_n * 56 + nt * 8 + tig * 2;
        if (p < HW) {
            size_t i0 = ((size_t)(bi * CCH + co) * TT + ti) * HW + p;
            float2 r0 = *(const float2*)&x[i0];
            float2 o0 = { acc[nt][0] + r0.x, acc[nt][1] + r0.y };
            *(float2*)&out[i0] = o0;
            size_t i1 = ((size_t)(bi * CCH + co + 8) * TT + ti) * HW + p;
            float2 r1 = *(const float2*)&x[i1];
            float2 o1 = { acc[nt][2] + r1.x, acc[nt][3] + r1.y };
            *(float2*)&out[i1] = o1;
        }
    }
}

// ---------------------------- host launch -----------------------------------
extern "C" void kernel_launch(void* const* d_in, const int* in_sizes, int n_in,
                              void* d_out, int out_size) {
    const float* x = (const float*)d_in[0];   // (8,1024,4,14,14)
    const float* W = (const float*)d_in[1];   // (1024,1024,3,3)
    float* out = (float*)d_out;

    prep_all<<<1024 + 7 * 32 * 32, 256>>>(W, x);

    cudaFuncSetAttribute(conv_mma, cudaFuncAttributeMaxDynamicSharedMemorySize, SMEM_REQ);
    conv_mma<<<1024, 256, SMEM_REQ>>>(x, out);
}